// round 1
// baseline (speedup 1.0000x reference)
#include <cuda_runtime.h>
#include <cuda_bf16.h>
#include <math.h>

// PointNetKAN: 10 Jacobi-KAN(deg 3) layers + per-channel BN + global maxpool/concat.
// Layer-6 trick: the broadcast global feature contributes an n-independent bias,
// so layer 6 becomes a 64-channel GEMM + per-(b,o) bias (73G MACs -> 4.4G).

#define BB 32
#define NN 1024
#define NPTS (BB * NN)
#define EPSV 1e-5f

// ---------------- scratch (device globals; no allocation allowed) ----------------
__device__ __align__(16) float g_bufA[32u * 1024u * 1024u];  // up to 1024 ch (y1,y3,y5,y7,y9)
__device__ __align__(16) float g_bufB[32u * 512u * 1024u];   // up to 512 ch (y4,y6,y8)
__device__ __align__(16) float g_y2[32u * 64u * 1024u];      // local_feature (raw, pre-BN)
__device__ float g_mean[10 * 1024];
__device__ float g_rstd[10 * 1024];
__device__ float g_gf[32 * 1024];                            // raw channel max per (b,c)
__device__ __align__(16) float g_gpoly[32 * 1024 * 4];       // polys of normalized gf
__device__ float g_bias6[32 * 512];

// ---------------- Jacobi polys (a=b=1, degree 3) ----------------
__device__ __forceinline__ void jacobi4(float t, float& p1, float& p2, float& p3) {
    p1 = 2.0f * t;
    p2 = 3.75f * t * t - 0.75f;
    p3 = (56.0f / 30.0f) * t * p2 - 0.8f * p1;
}

// ---------------- fused BN+tanh+poly GEMM ----------------
// in:  (BB, CIN, NN) raw (BN applied on the fly if mean != null)
// w:   (CIN_total, COUT, 4), row stride COUT*4 (works for the 1088-row w6 too)
// out: (BB, COUT, NN) raw (pre-BN)
template <int CIN, int COUT, int TO>
__global__ void kan_gemm(const float* __restrict__ in,
                         const float* __restrict__ mean,
                         const float* __restrict__ rstd,
                         const float* __restrict__ w,
                         const float* __restrict__ bias,
                         float* __restrict__ out) {
    constexpr int TP = 64;                    // points per block
    constexpr int KC = (CIN < 8) ? CIN : 8;   // channels per K-chunk
    constexpr int KR = KC * 4;                // poly rows per chunk
    constexpr int NR = TO / 16;               // outputs per thread (4 or 8)

    __shared__ __align__(16) float As[KR][TP + 4];
    __shared__ __align__(16) float Bs[KR][TO + 4];

    const int tid = threadIdx.x;              // 256 threads: 16 (pts) x 16 (outs)
    const int tx = tid & 15;
    const int ty = tid >> 4;
    const int g0 = blockIdx.x * TP;
    const int b = g0 >> 10;
    const int n0 = g0 & 1023;
    const int o0 = blockIdx.y * TO;

    float acc[4][NR];
#pragma unroll
    for (int m = 0; m < 4; m++)
#pragma unroll
        for (int j = 0; j < NR; j++) acc[m][j] = 0.0f;

    for (int c0 = 0; c0 < CIN; c0 += KC) {
        // --- load + transform A: raw -> BN -> tanh -> 4 Jacobi rows ---
#pragma unroll
        for (int e = tid; e < KC * TP; e += 256) {
            int c = e / TP, p = e % TP;
            float v = in[((size_t)(b * CIN + c0 + c)) * NN + n0 + p];
            if (mean) v = (v - mean[c0 + c]) * rstd[c0 + c];
            float t = tanhf(v);
            float p1, p2, p3;
            jacobi4(t, p1, p2, p3);
            As[c * 4 + 0][p] = 1.0f;
            As[c * 4 + 1][p] = p1;
            As[c * 4 + 2][p] = p2;
            As[c * 4 + 3][p] = p3;
        }
        // --- load B: w[(c,o,0..3)] as float4, scatter to 4 rows ---
#pragma unroll
        for (int e = tid; e < KC * TO; e += 256) {
            int c = e / TO, o = e % TO;
            float4 v = *(const float4*)&w[((size_t)(c0 + c) * COUT + (o0 + o)) * 4];
            Bs[c * 4 + 0][o] = v.x;
            Bs[c * 4 + 1][o] = v.y;
            Bs[c * 4 + 2][o] = v.z;
            Bs[c * 4 + 3][o] = v.w;
        }
        __syncthreads();
#pragma unroll
        for (int k = 0; k < KR; k++) {
            float4 a = *(const float4*)&As[k][tx * 4];
            float bv[NR];
#pragma unroll
            for (int j = 0; j < NR; j += 4) {
                float4 t4 = *(const float4*)&Bs[k][ty * NR + j];
                bv[j] = t4.x; bv[j + 1] = t4.y; bv[j + 2] = t4.z; bv[j + 3] = t4.w;
            }
#pragma unroll
            for (int j = 0; j < NR; j++) {
                acc[0][j] += a.x * bv[j];
                acc[1][j] += a.y * bv[j];
                acc[2][j] += a.z * bv[j];
                acc[3][j] += a.w * bv[j];
            }
        }
        __syncthreads();
    }
#pragma unroll
    for (int j = 0; j < NR; j++) {
        int o = o0 + ty * NR + j;
        float bb = bias ? bias[b * COUT + o] : 0.0f;
        float4 v;
        v.x = acc[0][j] + bb;
        v.y = acc[1][j] + bb;
        v.z = acc[2][j] + bb;
        v.w = acc[3][j] + bb;
        *(float4*)&out[((size_t)(b * COUT + o)) * NN + n0 + tx * 4] = v;
    }
}

// ---------------- per-channel mean/rstd over (b, n) ----------------
__global__ void stats_kernel(const float* __restrict__ y, int C,
                             float* __restrict__ mean, float* __restrict__ rstd) {
    int c = blockIdx.x;
    double s = 0.0, ss = 0.0;
    for (int b = 0; b < BB; b++) {
        const float* row = y + ((size_t)(b * C + c)) * NN;
        for (int n = threadIdx.x; n < NN; n += 256) {
            float v = row[n];
            s += v;
            ss += (double)v * v;
        }
    }
    __shared__ double sh[256], sh2[256];
    sh[threadIdx.x] = s;
    sh2[threadIdx.x] = ss;
    __syncthreads();
    for (int st = 128; st > 0; st >>= 1) {
        if (threadIdx.x < st) {
            sh[threadIdx.x] += sh[threadIdx.x + st];
            sh2[threadIdx.x] += sh2[threadIdx.x + st];
        }
        __syncthreads();
    }
    if (threadIdx.x == 0) {
        double m = sh[0] / (double)NPTS;
        double var = sh2[0] / (double)NPTS - m * m;
        mean[c] = (float)m;
        rstd[c] = rsqrtf((float)var + EPSV);
    }
}

// ---------------- max over n per (b, c) ----------------
__global__ void maxpool_kernel(const float* __restrict__ y, float* __restrict__ gf) {
    const float* row = y + (size_t)blockIdx.x * NN;  // blockIdx.x = b*1024 + c
    float m = -3.4e38f;
    for (int n = threadIdx.x; n < NN; n += 256) m = fmaxf(m, row[n]);
    __shared__ float sh[256];
    sh[threadIdx.x] = m;
    __syncthreads();
    for (int st = 128; st > 0; st >>= 1) {
        if (threadIdx.x < st) sh[threadIdx.x] = fmaxf(sh[threadIdx.x], sh[threadIdx.x + st]);
        __syncthreads();
    }
    if (threadIdx.x == 0) gf[blockIdx.x] = sh[0];
}

// ---------------- polys of normalized gf ----------------
__global__ void gpoly_kernel(const float* __restrict__ gf, const float* __restrict__ mean5,
                             const float* __restrict__ rstd5, float* __restrict__ gp) {
    int i = blockIdx.x * blockDim.x + threadIdx.x;  // 32768 = b*1024 + c
    int c = i & 1023;
    float t = tanhf((gf[i] - mean5[c]) * rstd5[c]);
    float p1, p2, p3;
    jacobi4(t, p1, p2, p3);
    float4 v;
    v.x = 1.0f; v.y = p1; v.z = p2; v.w = p3;
    ((float4*)gp)[i] = v;
}

// ---------------- layer-6 bias from gf rows of w6 ----------------
__global__ void bias6_kernel(const float* __restrict__ gp, const float* __restrict__ w6,
                             float* __restrict__ bias) {
    int b = blockIdx.x;                        // 32
    int o = blockIdx.y * 64 + threadIdx.x;     // 512
    const float4* g4 = (const float4*)(gp + (size_t)b * 4096);
    float acc = 0.0f;
    for (int j = 0; j < 1024; j++) {
        float4 g = g4[j];
        float4 wv = *(const float4*)&w6[((size_t)(64 + j) * 512 + o) * 4];
        acc += g.x * wv.x + g.y * wv.y + g.z * wv.z + g.w * wv.w;
    }
    bias[b * 512 + o] = acc;
}

// ---------------- final layer: 128 -> 3, no BN after ----------------
__global__ void final_kernel(const float* __restrict__ in, const float* __restrict__ mean,
                             const float* __restrict__ rstd, const float* __restrict__ w,
                             float* __restrict__ out) {
    __shared__ float ws[128 * 12];
    for (int e = threadIdx.x; e < 1536; e += 256) ws[e] = w[e];
    __syncthreads();
    int g = blockIdx.x * 256 + threadIdx.x;
    int b = g >> 10, n = g & 1023;
    float a0 = 0.0f, a1 = 0.0f, a2 = 0.0f;
    for (int c = 0; c < 128; c++) {
        float v = in[((size_t)(b * 128 + c)) * NN + n];
        v = (v - mean[c]) * rstd[c];
        float t = tanhf(v);
        float p1, p2, p3;
        jacobi4(t, p1, p2, p3);
        const float* wc = &ws[c * 12];
        a0 += wc[0] + p1 * wc[1] + p2 * wc[2] + p3 * wc[3];
        a1 += wc[4] + p1 * wc[5] + p2 * wc[6] + p3 * wc[7];
        a2 += wc[8] + p1 * wc[9] + p2 * wc[10] + p3 * wc[11];
    }
    out[((size_t)(b * 3 + 0)) * NN + n] = a0;
    out[((size_t)(b * 3 + 1)) * NN + n] = a1;
    out[((size_t)(b * 3 + 2)) * NN + n] = a2;
}

extern "C" void kernel_launch(void* const* d_in, const int* in_sizes, int n_in,
                              void* d_out, int out_size) {
    const float* x = (const float*)d_in[0];
    const float* w1 = (const float*)d_in[1];
    const float* w2 = (const float*)d_in[2];
    const float* w3 = (const float*)d_in[3];
    const float* w4 = (const float*)d_in[4];
    const float* w5 = (const float*)d_in[5];
    const float* w6 = (const float*)d_in[6];
    const float* w7 = (const float*)d_in[7];
    const float* w8 = (const float*)d_in[8];
    const float* w9 = (const float*)d_in[9];
    const float* w10 = (const float*)d_in[10];

    float *bufA, *bufB, *y2, *sm, *sr, *gf, *gp, *b6;
    cudaGetSymbolAddress((void**)&bufA, g_bufA);
    cudaGetSymbolAddress((void**)&bufB, g_bufB);
    cudaGetSymbolAddress((void**)&y2, g_y2);
    cudaGetSymbolAddress((void**)&sm, g_mean);
    cudaGetSymbolAddress((void**)&sr, g_rstd);
    cudaGetSymbolAddress((void**)&gf, g_gf);
    cudaGetSymbolAddress((void**)&gp, g_gpoly);
    cudaGetSymbolAddress((void**)&b6, g_bias6);

    const int PT = NPTS / 64;  // 512 point tiles

    // L1: 2 -> 64
    kan_gemm<2, 64, 64><<<dim3(PT, 1), 256>>>(x, nullptr, nullptr, w1, nullptr, bufA);
    stats_kernel<<<64, 256>>>(bufA, 64, sm + 0, sr + 0);
    // L2: 64 -> 64 (keep raw y2 as local feature)
    kan_gemm<64, 64, 64><<<dim3(PT, 1), 256>>>(bufA, sm + 0, sr + 0, w2, nullptr, y2);
    stats_kernel<<<64, 256>>>(y2, 64, sm + 1024, sr + 1024);
    // L3: 64 -> 64
    kan_gemm<64, 64, 64><<<dim3(PT, 1), 256>>>(y2, sm + 1024, sr + 1024, w3, nullptr, bufA);
    stats_kernel<<<64, 256>>>(bufA, 64, sm + 2048, sr + 2048);
    // L4: 64 -> 128
    kan_gemm<64, 128, 128><<<dim3(PT, 1), 256>>>(bufA, sm + 2048, sr + 2048, w4, nullptr, bufB);
    stats_kernel<<<128, 256>>>(bufB, 128, sm + 3072, sr + 3072);
    // L5: 128 -> 1024
    kan_gemm<128, 1024, 128><<<dim3(PT, 8), 256>>>(bufB, sm + 3072, sr + 3072, w5, nullptr, bufA);
    stats_kernel<<<1024, 256>>>(bufA, 1024, sm + 4096, sr + 4096);
    // global feature: max over n, then polys of normalized max, then layer-6 bias
    maxpool_kernel<<<32 * 1024, 256>>>(bufA, gf);
    gpoly_kernel<<<128, 256>>>(gf, sm + 4096, sr + 4096, gp);
    bias6_kernel<<<dim3(32, 8), 64>>>(gp, w6, b6);
    // L6: concat(64 local + 1024 gf) -> 512, gf part folded into bias
    kan_gemm<64, 512, 128><<<dim3(PT, 4), 256>>>(y2, sm + 1024, sr + 1024, w6, b6, bufB);
    stats_kernel<<<512, 256>>>(bufB, 512, sm + 5120, sr + 5120);
    // L7: 512 -> 256
    kan_gemm<512, 256, 128><<<dim3(PT, 2), 256>>>(bufB, sm + 5120, sr + 5120, w7, nullptr, bufA);
    stats_kernel<<<256, 256>>>(bufA, 256, sm + 6144, sr + 6144);
    // L8: 256 -> 128
    kan_gemm<256, 128, 128><<<dim3(PT, 1), 256>>>(bufA, sm + 6144, sr + 6144, w8, nullptr, bufB);
    stats_kernel<<<128, 256>>>(bufB, 128, sm + 7168, sr + 7168);
    // L9: 128 -> 128
    kan_gemm<128, 128, 128><<<dim3(PT, 1), 256>>>(bufB, sm + 7168, sr + 7168, w9, nullptr, bufA);
    stats_kernel<<<128, 256>>>(bufA, 128, sm + 8192, sr + 8192);
    // L10: 128 -> 3 (no BN)
    final_kernel<<<128, 256>>>(bufA, sm + 8192, sr + 8192, w10, (float*)d_out);
}

// round 2
// speedup vs baseline: 1.6150x; 1.6150x over previous
#include <cuda_runtime.h>
#include <math.h>

// PointNetKAN on GB300. Round 2:
//  - packed fma.rn.f32x2 GEMM core (2x scalar-FFMA ceiling)
//  - P0(==1) Jacobi row folded into a per-layer constant bias (-25% MACs)
//  - BN stats + global maxpool fused into GEMM epilogue (atomics), tiny finalize kernels
//  - layer-6 broadcast-gf contribution collapsed to per-(b,o) bias (73G->4.4G MACs)

#define BB 32
#define NN 1024
#define NPTS (BB * NN)
#define EPSV 1e-5f

typedef unsigned long long u64;
typedef unsigned int u32;

// ---------------- scratch (device globals; no allocation allowed) ----------------
__device__ __align__(16) float g_bufA[32u * 1024u * 1024u];
__device__ __align__(16) float g_bufB[32u * 512u * 1024u];
__device__ __align__(16) float g_y2[32u * 64u * 1024u];      // local_feature (raw, pre-BN)
__device__ float g_mean[10 * 1024];
__device__ float g_rstd[10 * 1024];
__device__ double g_dsum[10 * 1024];
__device__ double g_dss[10 * 1024];
__device__ u32 g_maxkey[32 * 1024];
__device__ __align__(16) float g_gpoly[32 * 1024 * 4];
__device__ float g_bias6[32 * 512];
__device__ float g_cbias[10 * 1024];

// ---------------- helpers ----------------
__device__ __forceinline__ u64 dup2(float x) {
    u64 d; u32 u = __float_as_uint(x);
    asm("mov.b64 %0, {%1, %1};" : "=l"(d) : "r"(u));
    return d;
}
__device__ __forceinline__ void fma2(u64& d, u64 a, u64 b) {
    asm("fma.rn.f32x2 %0, %1, %2, %0;" : "+l"(d) : "l"(a), "l"(b));
}
__device__ __forceinline__ void unpack2(u64 v, float& lo, float& hi) {
    u32 a, b; asm("mov.b64 {%0, %1}, %2;" : "=r"(a), "=r"(b) : "l"(v));
    lo = __uint_as_float(a); hi = __uint_as_float(b);
}
// order-preserving float <-> uint map for atomicMax (init value 0 == -infinity-)
__device__ __forceinline__ u32 fkey(float f) {
    u32 u = __float_as_uint(f);
    return (u & 0x80000000u) ? ~u : (u | 0x80000000u);
}
__device__ __forceinline__ float finv(u32 k) {
    u32 u = (k & 0x80000000u) ? (k ^ 0x80000000u) : ~k;
    return __uint_as_float(u);
}
__device__ __forceinline__ void jacobi3(float t, float& p1, float& p2, float& p3) {
    p1 = 2.0f * t;
    p2 = 3.75f * t * t - 0.75f;
    p3 = (56.0f / 30.0f) * t * p2 - 0.8f * p1;
}

// ---------------- fused BN+tanh+poly GEMM with f32x2 core ----------------
// in:  (BB, CIN, NN) raw (BN on the fly if mean != null)
// w:   (CIN_total, COUT, 4), only poly rows 1..3 enter the GEMM
// out: (BB, COUT, NN) raw (pre-BN); per-channel sums/ss (+max) accumulated via atomics
template <int CIN, int COUT, int TO, bool DOMAX>
__global__ __launch_bounds__(256, 2) void kan_gemm(
    const float* __restrict__ in, const float* __restrict__ mean,
    const float* __restrict__ rstd, const float* __restrict__ w,
    const float* __restrict__ cbias, const float* __restrict__ bias,
    float* __restrict__ out, double* __restrict__ dsum,
    double* __restrict__ dss, u32* __restrict__ maxkey) {
    constexpr int TP = 128;                  // points per block
    constexpr int KC = (CIN < 8) ? CIN : 8;  // channels per K-chunk
    constexpr int KR = KC * 3;               // poly rows per chunk (P1..P3)
    constexpr int NR = TO / 16;              // outputs per thread

    __shared__ __align__(16) float As[KR][TP + 4];
    __shared__ __align__(16) float Bs[KR][TO + 4];

    const int tid = threadIdx.x;             // 256 = 16 (pts) x 16 (outs)
    const int tx = tid & 15;                 // 8 points each
    const int ty = tid >> 4;                 // NR outs each
    const int g0 = blockIdx.x * TP;
    const int b = g0 >> 10;
    const int n0 = g0 & 1023;
    const int o0 = blockIdx.y * TO;

    u64 acc[4][NR];
#pragma unroll
    for (int p = 0; p < 4; p++)
#pragma unroll
        for (int j = 0; j < NR; j++) acc[p][j] = 0ull;

    for (int c0 = 0; c0 < CIN; c0 += KC) {
        // A: raw -> BN -> tanh -> 3 Jacobi rows
#pragma unroll
        for (int e = tid; e < KC * TP; e += 256) {
            int c = e / TP, p = e - c * TP;
            float v = in[((size_t)(b * CIN + c0 + c)) * NN + n0 + p];
            if (mean) v = (v - mean[c0 + c]) * rstd[c0 + c];
            float t = tanhf(v);
            float p1, p2, p3;
            jacobi3(t, p1, p2, p3);
            As[c * 3 + 0][p] = p1;
            As[c * 3 + 1][p] = p2;
            As[c * 3 + 2][p] = p3;
        }
        // B: w[(c,o,1..3)] scattered to 3 rows
#pragma unroll
        for (int e = tid; e < KC * TO; e += 256) {
            int c = e / TO, o = e - c * TO;
            float4 v = *(const float4*)&w[((size_t)(c0 + c) * COUT + (o0 + o)) * 4];
            Bs[c * 3 + 0][o] = v.y;
            Bs[c * 3 + 1][o] = v.z;
            Bs[c * 3 + 2][o] = v.w;
        }
        __syncthreads();
#pragma unroll 8
        for (int k = 0; k < KR; k++) {
            ulonglong2 a01 = *(const ulonglong2*)&As[k][tx * 8];
            ulonglong2 a23 = *(const ulonglong2*)&As[k][tx * 8 + 4];
            u64 av[4] = {a01.x, a01.y, a23.x, a23.y};
            u64 bb[NR];
#pragma unroll
            for (int j = 0; j < NR; j += 4) {
                float4 w4 = *(const float4*)&Bs[k][ty * NR + j];
                bb[j + 0] = dup2(w4.x);
                bb[j + 1] = dup2(w4.y);
                bb[j + 2] = dup2(w4.z);
                bb[j + 3] = dup2(w4.w);
            }
#pragma unroll
            for (int j = 0; j < NR; j++)
#pragma unroll
                for (int p = 0; p < 4; p++) fma2(acc[p][j], av[p], bb[j]);
        }
        __syncthreads();
    }

    // epilogue: bias add, store, fused per-channel stats (+max)
#pragma unroll
    for (int j = 0; j < NR; j++) {
        int o = o0 + ty * NR + j;
        float add = cbias[o] + (bias ? bias[b * COUT + o] : 0.0f);
        float v[8];
#pragma unroll
        for (int p = 0; p < 4; p++) unpack2(acc[p][j], v[2 * p], v[2 * p + 1]);
        float s = 0.0f, ss = 0.0f, mx = -3.4e38f;
#pragma unroll
        for (int p = 0; p < 8; p++) {
            v[p] += add;
            s += v[p];
            ss += v[p] * v[p];
            if (DOMAX) mx = fmaxf(mx, v[p]);
        }
        float* op = &out[((size_t)(b * COUT + o)) * NN + n0 + tx * 8];
        *(float4*)op = make_float4(v[0], v[1], v[2], v[3]);
        *(float4*)(op + 4) = make_float4(v[4], v[5], v[6], v[7]);
        // reduce across the 16 tx threads (contiguous 16-lane segment of the warp)
#pragma unroll
        for (int off = 8; off; off >>= 1) {
            s += __shfl_down_sync(0xffffffffu, s, off, 16);
            ss += __shfl_down_sync(0xffffffffu, ss, off, 16);
            if (DOMAX) mx = fmaxf(mx, __shfl_down_sync(0xffffffffu, mx, off, 16));
        }
        if (tx == 0) {
            atomicAdd(&dsum[o], (double)s);
            atomicAdd(&dss[o], (double)ss);
            if (DOMAX) atomicMax(&maxkey[b * 1024 + o], fkey(mx));
        }
    }
}

// ---------------- per-layer constant bias: sum over channels of w[c][o][0] ----------------
__global__ void cbias_kernel(const float* __restrict__ w, int CIN, int COUT,
                             float* __restrict__ cb) {
    int o = blockIdx.x * 256 + threadIdx.x;
    if (o >= COUT) return;
    float s = 0.0f;
    for (int c = 0; c < CIN; c++) s += w[((size_t)c * COUT + o) * 4];
    cb[o] = s;
}

// ---------------- finalize mean/rstd from double accumulators ----------------
__global__ void fin_kernel(const double* __restrict__ dsum, const double* __restrict__ dss,
                           int C, float* __restrict__ mean, float* __restrict__ rstd) {
    int c = blockIdx.x * blockDim.x + threadIdx.x;
    if (c >= C) return;
    double m = dsum[c] / (double)NPTS;
    double v = dss[c] / (double)NPTS - m * m;
    mean[c] = (float)m;
    rstd[c] = rsqrtf((float)v + EPSV);
}

// ---------------- polys of normalized gf (from ordered-int max keys) ----------------
__global__ void gpoly_kernel(const u32* __restrict__ mk, const float* __restrict__ mean5,
                             const float* __restrict__ rstd5, float* __restrict__ gp) {
    int i = blockIdx.x * blockDim.x + threadIdx.x;  // 32768 = b*1024 + c
    int c = i & 1023;
    float g = finv(mk[i]);
    float t = tanhf((g - mean5[c]) * rstd5[c]);
    float p1, p2, p3;
    jacobi3(t, p1, p2, p3);
    ((float4*)gp)[i] = make_float4(1.0f, p1, p2, p3);
}

// ---------------- layer-6 bias from gf rows of w6 (includes their P0 part) ----------------
__global__ void bias6_kernel(const float* __restrict__ gp, const float* __restrict__ w6,
                             float* __restrict__ bias) {
    int b = blockIdx.x;                     // 32
    int o = blockIdx.y * 64 + threadIdx.x;  // 512
    const float4* g4 = (const float4*)(gp + (size_t)b * 4096);
    float acc = 0.0f;
    for (int j = 0; j < 1024; j++) {
        float4 g = g4[j];
        float4 wv = *(const float4*)&w6[((size_t)(64 + j) * 512 + o) * 4];
        acc += g.x * wv.x + g.y * wv.y + g.z * wv.z + g.w * wv.w;
    }
    bias[b * 512 + o] = acc;
}

// ---------------- final layer: 128 -> 3, no BN after ----------------
__global__ void final_kernel(const float* __restrict__ in, const float* __restrict__ mean,
                             const float* __restrict__ rstd, const float* __restrict__ w,
                             float* __restrict__ out) {
    __shared__ float ws[128 * 12];
    for (int e = threadIdx.x; e < 1536; e += 256) ws[e] = w[e];
    __syncthreads();
    int g = blockIdx.x * 256 + threadIdx.x;
    int b = g >> 10, n = g & 1023;
    float a0 = 0.0f, a1 = 0.0f, a2 = 0.0f;
    for (int c = 0; c < 128; c++) {
        float v = in[((size_t)(b * 128 + c)) * NN + n];
        v = (v - mean[c]) * rstd[c];
        float t = tanhf(v);
        float p1, p2, p3;
        jacobi3(t, p1, p2, p3);
        const float* wc = &ws[c * 12];
        a0 += wc[0] + p1 * wc[1] + p2 * wc[2] + p3 * wc[3];
        a1 += wc[4] + p1 * wc[5] + p2 * wc[6] + p3 * wc[7];
        a2 += wc[8] + p1 * wc[9] + p2 * wc[10] + p3 * wc[11];
    }
    out[((size_t)(b * 3 + 0)) * NN + n] = a0;
    out[((size_t)(b * 3 + 1)) * NN + n] = a1;
    out[((size_t)(b * 3 + 2)) * NN + n] = a2;
}

extern "C" void kernel_launch(void* const* d_in, const int* in_sizes, int n_in,
                              void* d_out, int out_size) {
    const float* x = (const float*)d_in[0];
    const float* w1 = (const float*)d_in[1];
    const float* w2 = (const float*)d_in[2];
    const float* w3 = (const float*)d_in[3];
    const float* w4 = (const float*)d_in[4];
    const float* w5 = (const float*)d_in[5];
    const float* w6 = (const float*)d_in[6];
    const float* w7 = (const float*)d_in[7];
    const float* w8 = (const float*)d_in[8];
    const float* w9 = (const float*)d_in[9];
    const float* w10 = (const float*)d_in[10];

    float *bufA, *bufB, *y2, *sm, *sr, *gp, *b6, *cb;
    double *dsum, *dss;
    u32* mk;
    cudaGetSymbolAddress((void**)&bufA, g_bufA);
    cudaGetSymbolAddress((void**)&bufB, g_bufB);
    cudaGetSymbolAddress((void**)&y2, g_y2);
    cudaGetSymbolAddress((void**)&sm, g_mean);
    cudaGetSymbolAddress((void**)&sr, g_rstd);
    cudaGetSymbolAddress((void**)&dsum, g_dsum);
    cudaGetSymbolAddress((void**)&dss, g_dss);
    cudaGetSymbolAddress((void**)&mk, g_maxkey);
    cudaGetSymbolAddress((void**)&gp, g_gpoly);
    cudaGetSymbolAddress((void**)&b6, g_bias6);
    cudaGetSymbolAddress((void**)&cb, g_cbias);

    // zero the atomic accumulators (replayed as graph memset nodes)
    cudaMemsetAsync(dsum, 0, 10 * 1024 * sizeof(double));
    cudaMemsetAsync(dss, 0, 10 * 1024 * sizeof(double));
    cudaMemsetAsync(mk, 0, 32 * 1024 * sizeof(u32));

    // per-layer P0 constant biases (independent of activations; run up front)
    cbias_kernel<<<1, 256>>>(w1, 2, 64, cb + 0);
    cbias_kernel<<<1, 256>>>(w2, 64, 64, cb + 1024);
    cbias_kernel<<<1, 256>>>(w3, 64, 64, cb + 2048);
    cbias_kernel<<<1, 256>>>(w4, 64, 128, cb + 3072);
    cbias_kernel<<<4, 256>>>(w5, 128, 1024, cb + 4096);
    cbias_kernel<<<2, 256>>>(w6, 64, 512, cb + 5120);  // local rows only
    cbias_kernel<<<1, 256>>>(w7, 512, 256, cb + 6144);
    cbias_kernel<<<1, 256>>>(w8, 256, 128, cb + 7168);
    cbias_kernel<<<1, 256>>>(w9, 128, 128, cb + 8192);

    const int PT = NPTS / 128;  // 256 point tiles

    // L1: 2 -> 64
    kan_gemm<2, 64, 64, false><<<dim3(PT, 1), 256>>>(x, nullptr, nullptr, w1, cb + 0, nullptr,
                                                     bufA, dsum + 0, dss + 0, nullptr);
    fin_kernel<<<1, 256>>>(dsum + 0, dss + 0, 64, sm + 0, sr + 0);
    // L2: 64 -> 64 (keep raw y2 as local feature)
    kan_gemm<64, 64, 64, false><<<dim3(PT, 1), 256>>>(bufA, sm + 0, sr + 0, w2, cb + 1024,
                                                      nullptr, y2, dsum + 1024, dss + 1024, nullptr);
    fin_kernel<<<1, 256>>>(dsum + 1024, dss + 1024, 64, sm + 1024, sr + 1024);
    // L3: 64 -> 64
    kan_gemm<64, 64, 64, false><<<dim3(PT, 1), 256>>>(y2, sm + 1024, sr + 1024, w3, cb + 2048,
                                                      nullptr, bufA, dsum + 2048, dss + 2048, nullptr);
    fin_kernel<<<1, 256>>>(dsum + 2048, dss + 2048, 64, sm + 2048, sr + 2048);
    // L4: 64 -> 128
    kan_gemm<64, 128, 128, false><<<dim3(PT, 1), 256>>>(bufA, sm + 2048, sr + 2048, w4, cb + 3072,
                                                        nullptr, bufB, dsum + 3072, dss + 3072, nullptr);
    fin_kernel<<<1, 256>>>(dsum + 3072, dss + 3072, 128, sm + 3072, sr + 3072);
    // L5: 128 -> 1024 (fused maxpool)
    kan_gemm<128, 1024, 128, true><<<dim3(PT, 8), 256>>>(bufB, sm + 3072, sr + 3072, w5, cb + 4096,
                                                         nullptr, bufA, dsum + 4096, dss + 4096, mk);
    fin_kernel<<<4, 256>>>(dsum + 4096, dss + 4096, 1024, sm + 4096, sr + 4096);
    // global feature path
    gpoly_kernel<<<128, 256>>>(mk, sm + 4096, sr + 4096, gp);
    bias6_kernel<<<dim3(32, 8), 64>>>(gp, w6, b6);
    // L6: concat(64 local + 1024 gf) -> 512, gf part folded into per-(b,o) bias
    kan_gemm<64, 512, 128, false><<<dim3(PT, 4), 256>>>(y2, sm + 1024, sr + 1024, w6, cb + 5120,
                                                        b6, bufB, dsum + 5120, dss + 5120, nullptr);
    fin_kernel<<<2, 256>>>(dsum + 5120, dss + 5120, 512, sm + 5120, sr + 5120);
    // L7: 512 -> 256
    kan_gemm<512, 256, 128, false><<<dim3(PT, 2), 256>>>(bufB, sm + 5120, sr + 5120, w7, cb + 6144,
                                                         nullptr, bufA, dsum + 6144, dss + 6144, nullptr);
    fin_kernel<<<1, 256>>>(dsum + 6144, dss + 6144, 256, sm + 6144, sr + 6144);
    // L8: 256 -> 128
    kan_gemm<256, 128, 128, false><<<dim3(PT, 1), 256>>>(bufA, sm + 6144, sr + 6144, w8, cb + 7168,
                                                         nullptr, bufB, dsum + 7168, dss + 7168, nullptr);
    fin_kernel<<<1, 256>>>(dsum + 7168, dss + 7168, 128, sm + 7168, sr + 7168);
    // L9: 128 -> 128
    kan_gemm<128, 128, 128, false><<<dim3(PT, 1), 256>>>(bufB, sm + 7168, sr + 7168, w9, cb + 8192,
                                                         nullptr, bufA, dsum + 8192, dss + 8192, nullptr);
    fin_kernel<<<1, 256>>>(dsum + 8192, dss + 8192, 128, sm + 8192, sr + 8192);
    // L10: 128 -> 3 (no BN)
    final_kernel<<<128, 256>>>(bufA, sm + 8192, sr + 8192, w10, (float*)d_out);
}